// round 4
// baseline (speedup 1.0000x reference)
#include <cuda_runtime.h>

#define BB 4
#define NN 512
#define DD 64
#define EPS 1e-5f
#define NEG_SLOPE 0.01f
#define TI 4
#define THREADS 512

// Scratch + sync flag (allocation-free __device__ globals)
__device__ float    g_sq[BB * NN];
__device__ float    g_sk[BB * NN];
__device__ unsigned g_done;   // zero-init; monotonic across replays (rewrites are bit-identical, so stale reads stay correct)

__device__ __forceinline__ unsigned ld_acquire(const unsigned* p) {
    unsigned v;
    asm volatile("ld.acquire.gpu.u32 %0, [%1];" : "=r"(v) : "l"(p));
    return v;
}

// ---------------------------------------------------------------------------
// Single launch, block-specialized.
// grid = BB * NN / TI = 512 blocks, 512 threads (8192 warps -> ~86% occ cap).
// Block blk: b = blk>>7, i-tile = (blk&127)*TI.
//  - blocks 0..31 first do LN + sq/sk projection for 64 rows each, release.
//  - all blocks: value stream for their TI i-rows; j outer (32 j per iter),
//    i inner -> each j-row float4 read once from L2, reused TI times.
//    Stores: warp writes 512 contiguous bytes (STG.128, streaming).
//  - all blocks: softmax + alphas for their TI i-rows (1 j per thread);
//    acquire-spin is free by then (LN done ~20 us earlier).
// ---------------------------------------------------------------------------
__global__ void __launch_bounds__(THREADS)
fused_attn(const float* __restrict__ x,
           const float* __restrict__ Wa,
           const float* __restrict__ ba,
           const float* __restrict__ gamma,
           const float* __restrict__ beta,
           float* __restrict__ alphas,
           float* __restrict__ value) {
    const int t    = threadIdx.x;
    const int lane = t & 31;
    const int w    = t >> 5;           // warp 0..15
    const int blk  = blockIdx.x;
    const int b    = blk >> 7;
    const int i0   = (blk & 127) * TI;

    __shared__ float red[16];

    // ---- LN + projection role: blocks 0..31, 64 rows each (16 warps) ----
    if (blk < 32) {
        const int bb = blk >> 3;           // batch
        const int r0 = (blk & 7) * 64;     // first row
        const float wq0 = Wa[lane],      wq1 = Wa[lane + 32];
        const float wk0 = Wa[64 + lane], wk1 = Wa[96 + lane];
        const float g0  = gamma[lane],   g1  = gamma[lane + 32];
        const float be0 = beta[lane],    be1 = beta[lane + 32];

        #pragma unroll
        for (int rr = 0; rr < 64; rr += 16) {
            const int r = r0 + rr + w;
            const float* row = x + ((size_t)bb * NN + r) * DD;
            float x0 = row[lane];
            float x1 = row[lane + 32];

            float s = x0 + x1;
            #pragma unroll
            for (int o = 16; o; o >>= 1) s += __shfl_xor_sync(0xffffffffu, s, o);
            float mu = s * (1.0f / 64.0f);

            float d0 = x0 - mu, d1 = x1 - mu;
            float v = d0 * d0 + d1 * d1;
            #pragma unroll
            for (int o = 16; o; o >>= 1) v += __shfl_xor_sync(0xffffffffu, v, o);
            float inv = rsqrtf(v * (1.0f / 64.0f) + EPS);

            float xn0 = d0 * inv * g0 + be0;
            float xn1 = d1 * inv * g1 + be1;

            float sq = xn0 * wq0 + xn1 * wq1;
            float sk = xn0 * wk0 + xn1 * wk1;
            #pragma unroll
            for (int o = 16; o; o >>= 1) {
                sq += __shfl_xor_sync(0xffffffffu, sq, o);
                sk += __shfl_xor_sync(0xffffffffu, sk, o);
            }
            if (lane == 0) { g_sq[bb * NN + r] = sq; g_sk[bb * NN + r] = sk; }
        }
        __threadfence();
        __syncthreads();
        if (t == 0) atomicAdd(&g_done, 1u);
    }

    // ---- Value stream: TI i-rows, j outer (32 per iter) / i inner ----
    {
        const float4* xb = (const float4*)(x + (size_t)b * NN * DD);
        const int d4 = t & 15;          // float4 within 64-float row
        const int jl = t >> 4;          // 0..31 local j

        float4 a[TI];
        #pragma unroll
        for (int i = 0; i < TI; i++) a[i] = xb[(i0 + i) * 16 + d4];

        float4* o0 = (float4*)(value + ((size_t)(b * NN + i0)) * NN * DD);

        #pragma unroll 2
        for (int jc = 0; jc < NN; jc += 32) {
            const int idx = (jc + jl) * 16 + d4;
            const float4 v = __ldg(&xb[idx]);   // L2-hot
            #pragma unroll
            for (int i = 0; i < TI; i++) {
                float4 r;
                r.x = a[i].x * v.x;
                r.y = a[i].y * v.y;
                r.z = a[i].z * v.z;
                r.w = a[i].w * v.w;
                __stcs(o0 + (size_t)i * (NN * DD / 4) + idx, r);  // streaming store
            }
        }
    }

    // ---- Softmax + alphas for this block's TI i-rows (1 j per thread) ----
    {
        if (t == 0) { while (ld_acquire(&g_done) < 32u) { } }
        __syncthreads();

        const float ba0 = ba[0];
        const float skv = g_sk[b * NN + t];

        for (int i = 0; i < TI; i++) {
            const int rg = b * NN + i0 + i;
            float s = g_sq[rg] + skv + ba0;
            s = (s >= 0.0f) ? s : NEG_SLOPE * s;

            // block max over 512 scores
            float m = s;
            #pragma unroll
            for (int o = 16; o; o >>= 1)
                m = fmaxf(m, __shfl_xor_sync(0xffffffffu, m, o));
            if (lane == 0) red[w] = m;
            __syncthreads();
            float bm = red[0];
            #pragma unroll
            for (int k = 1; k < 16; k++) bm = fmaxf(bm, red[k]);
            __syncthreads();

            // exp + block sum
            float e = __expf(s - bm);
            float ts = e;
            #pragma unroll
            for (int o = 16; o; o >>= 1) ts += __shfl_xor_sync(0xffffffffu, ts, o);
            if (lane == 0) red[w] = ts;
            __syncthreads();
            float bs = red[0];
            #pragma unroll
            for (int k = 1; k < 16; k++) bs += red[k];
            __syncthreads();

            alphas[(size_t)rg * NN + t] = e * (1.0f / bs);
        }
    }
}

// ---------------------------------------------------------------------------
extern "C" void kernel_launch(void* const* d_in, const int* in_sizes, int n_in,
                              void* d_out, int out_size) {
    const float* i_em  = (const float*)d_in[0];
    const float* W_a   = (const float*)d_in[1];
    const float* b_a   = (const float*)d_in[2];
    const float* gamma = (const float*)d_in[3];
    const float* beta  = (const float*)d_in[4];
    float* out = (float*)d_out;

    float* alphas = out;
    float* value  = out + (size_t)BB * NN * NN;

    fused_attn<<<BB * NN / TI, THREADS>>>(i_em, W_a, b_a, gamma, beta,
                                          alphas, value);
}

// round 5
// speedup vs baseline: 1.1316x; 1.1316x over previous
#include <cuda_runtime.h>

#define BB 4
#define NN 512
#define DD 64
#define EPS 1e-5f
#define NEG_SLOPE 0.01f
#define TI 4
#define THREADS 512

// Scratch + sync flag (allocation-free __device__ globals)
__device__ float    g_sq[BB * NN];
__device__ float    g_sk[BB * NN];
__device__ unsigned g_done;   // zero-init; monotonic across replays (rewrites are bit-identical, so stale reads stay correct)

__device__ __forceinline__ unsigned ld_acquire(const unsigned* p) {
    unsigned v;
    asm volatile("ld.acquire.gpu.u32 %0, [%1];" : "=r"(v) : "l"(p));
    return v;
}

// ---------------------------------------------------------------------------
// Single launch, block-specialized. grid = 512 blocks x 512 threads.
// Block blk: b = blk>>7, i-tile = (blk&127)*TI.
//  - blocks 0..31: LN + sq/sk projections (64 rows each), then release flag.
//  - all blocks: value stream, j outer (32 j/iter) / i inner, software-
//    pipelined j-row prefetch; stores STG.128 streaming, warp writes 512
//    contiguous bytes.
//  - all blocks: softmax + alphas afterwards (spin is free by then).
// ---------------------------------------------------------------------------
__global__ void __launch_bounds__(THREADS, 3)
fused_attn(const float* __restrict__ x,
           const float* __restrict__ Wa,
           const float* __restrict__ ba,
           const float* __restrict__ gamma,
           const float* __restrict__ beta,
           float* __restrict__ alphas,
           float* __restrict__ value) {
    const int t    = threadIdx.x;
    const int lane = t & 31;
    const int w    = t >> 5;           // warp 0..15
    const int blk  = blockIdx.x;
    const int b    = blk >> 7;
    const int i0   = (blk & 127) * TI;

    __shared__ float red[16];

    // ---- LN + projection role: blocks 0..31, 64 rows each (16 warps) ----
    if (blk < 32) {
        const int bb = blk >> 3;
        const int r0 = (blk & 7) * 64;
        const float wq0 = Wa[lane],      wq1 = Wa[lane + 32];
        const float wk0 = Wa[64 + lane], wk1 = Wa[96 + lane];
        const float g0  = gamma[lane],   g1  = gamma[lane + 32];
        const float be0 = beta[lane],    be1 = beta[lane + 32];

        #pragma unroll
        for (int rr = 0; rr < 64; rr += 16) {
            const int r = r0 + rr + w;
            const float* row = x + ((size_t)bb * NN + r) * DD;
            float x0 = row[lane];
            float x1 = row[lane + 32];

            float s = x0 + x1;
            #pragma unroll
            for (int o = 16; o; o >>= 1) s += __shfl_xor_sync(0xffffffffu, s, o);
            float mu = s * (1.0f / 64.0f);

            float d0 = x0 - mu, d1 = x1 - mu;
            float v = d0 * d0 + d1 * d1;
            #pragma unroll
            for (int o = 16; o; o >>= 1) v += __shfl_xor_sync(0xffffffffu, v, o);
            float inv = rsqrtf(v * (1.0f / 64.0f) + EPS);

            float xn0 = d0 * inv * g0 + be0;
            float xn1 = d1 * inv * g1 + be1;

            float sq = xn0 * wq0 + xn1 * wq1;
            float sk = xn0 * wk0 + xn1 * wk1;
            #pragma unroll
            for (int o = 16; o; o >>= 1) {
                sq += __shfl_xor_sync(0xffffffffu, sq, o);
                sk += __shfl_xor_sync(0xffffffffu, sk, o);
            }
            if (lane == 0) { g_sq[bb * NN + r] = sq; g_sk[bb * NN + r] = sk; }
        }
        __threadfence();
        __syncthreads();
        if (t == 0) atomicAdd(&g_done, 1u);
    }

    // ---- Value stream: TI i-rows, j outer, software-pipelined loads ----
    {
        const float4* xb = (const float4*)(x + (size_t)b * NN * DD);
        const int d4 = t & 15;          // float4 within 64-float row
        const int jl = t >> 4;          // 0..31 local j

        float4 a[TI];
        #pragma unroll
        for (int i = 0; i < TI; i++) a[i] = xb[(i0 + i) * 16 + d4];

        // thread-fixed base offset; advance by 32 j-rows (512 float4) per iter
        const float4* src = xb + jl * 16 + d4;
        float4* dst = (float4*)(value + ((size_t)(b * NN + i0)) * NN * DD)
                      + jl * 16 + d4;

        float4 v = __ldg(src);          // prologue load (L2-hot)

        #pragma unroll 1
        for (int jc = 0; jc < NN - 32; jc += 32) {
            src += 512;
            const float4 vn = __ldg(src);        // prefetch next
            #pragma unroll
            for (int i = 0; i < TI; i++) {
                float4 r;
                r.x = a[i].x * v.x;
                r.y = a[i].y * v.y;
                r.z = a[i].z * v.z;
                r.w = a[i].w * v.w;
                __stcs(dst + (size_t)i * (NN * DD / 4), r);
            }
            dst += 512;
            v = vn;
        }
        // epilogue: last 32 j
        #pragma unroll
        for (int i = 0; i < TI; i++) {
            float4 r;
            r.x = a[i].x * v.x;
            r.y = a[i].y * v.y;
            r.z = a[i].z * v.z;
            r.w = a[i].w * v.w;
            __stcs(dst + (size_t)i * (NN * DD / 4), r);
        }
    }

    // ---- Softmax + alphas for this block's TI i-rows (1 j per thread) ----
    {
        if (t == 0) { while (ld_acquire(&g_done) < 32u) { } }
        __syncthreads();

        const float ba0 = ba[0];
        const float skv = g_sk[b * NN + t];

        for (int i = 0; i < TI; i++) {
            const int rg = b * NN + i0 + i;
            float s = g_sq[rg] + skv + ba0;
            s = (s >= 0.0f) ? s : NEG_SLOPE * s;

            float m = s;
            #pragma unroll
            for (int o = 16; o; o >>= 1)
                m = fmaxf(m, __shfl_xor_sync(0xffffffffu, m, o));
            if (lane == 0) red[w] = m;
            __syncthreads();
            float bm = red[0];
            #pragma unroll
            for (int k = 1; k < 16; k++) bm = fmaxf(bm, red[k]);
            __syncthreads();

            float e = __expf(s - bm);
            float ts = e;
            #pragma unroll
            for (int o = 16; o; o >>= 1) ts += __shfl_xor_sync(0xffffffffu, ts, o);
            if (lane == 0) red[w] = ts;
            __syncthreads();
            float bs = red[0];
            #pragma unroll
            for (int k = 1; k < 16; k++) bs += red[k];
            __syncthreads();

            alphas[(size_t)rg * NN + t] = e * (1.0f / bs);
        }
    }
}

// ---------------------------------------------------------------------------
extern "C" void kernel_launch(void* const* d_in, const int* in_sizes, int n_in,
                              void* d_out, int out_size) {
    const float* i_em  = (const float*)d_in[0];
    const float* W_a   = (const float*)d_in[1];
    const float* b_a   = (const float*)d_in[2];
    const float* gamma = (const float*)d_in[3];
    const float* beta  = (const float*)d_in[4];
    float* out = (float*)d_out;

    float* alphas = out;
    float* value  = out + (size_t)BB * NN * NN;

    fused_attn<<<BB * NN / TI, THREADS>>>(i_em, W_a, b_a, gamma, beta,
                                          alphas, value);
}